// round 3
// baseline (speedup 1.0000x reference)
#include <cuda_runtime.h>
#include <cstdint>

#define QN   10000
#define NCAM 6
#define DIM  256
#define HWF  2816     // 32*88
#define NH   8
#define HD   32
#define HFv  32
#define WFv  88
#define MROWS (NCAM*QN)   // 60000
#define OAC  192          // 128 offsets + 64 attn logits

#define BM 256
#define BN 64
#define BK 16
#define ASTR 260
#define BSTR 132

// ---------------- scratch ----------------
__device__ float d_value[NCAM*NH*HWF*HD];   // (cam, head, hw, hd)
__device__ float d_offattn[(size_t)MROWS*OAC];
__device__ float d_S[(size_t)QN*DIM];
__device__ float d_gflag[QN];
__device__ float d_bias2[NCAM*DIM];
__device__ float d_Wc[DIM*DIM];             // W_out @ W_inner
__device__ float d_bi2[DIM];                // W_out @ b_inner
__device__ int   d_mask_mode;               // 0=u8, 1=i32, 2=f32

// ---------------- helpers ----------------
__device__ __forceinline__ float2 u2f(unsigned long long v) {
    float2 f; asm("mov.b64 {%0,%1}, %2;" : "=f"(f.x), "=f"(f.y) : "l"(v)); return f;
}
__device__ __forceinline__ void ffma2(unsigned long long& acc, unsigned long long a,
                                      unsigned long long b) {
    asm("fma.rn.f32x2 %0, %1, %2, %0;" : "+l"(acc) : "l"(a), "l"(b));
}

// ---------------- mask dtype detection ----------------
__global__ void detect_mask(const unsigned int* __restrict__ m) {
    int t = threadIdx.x;
    bool f = false, multi = false;
    for (int i = t; i < 256; i += 32) {
        unsigned int w = m[i];
        f |= (w == 0x3F800000u);
        multi |= (w != 0x3F800000u && w > 1u);
    }
    unsigned bf = __ballot_sync(0xffffffffu, f), bm = __ballot_sync(0xffffffffu, multi);
    if (t == 0) d_mask_mode = bf ? 2 : (bm ? 0 : 1);
}

__device__ __forceinline__ int mask_elem(const void* mask, size_t idx, int mode) {
    if (mode == 0) return ((const unsigned char*)mask)[idx] != 0;
    if (mode == 1) return ((const int*)mask)[idx] != 0;
    return ((const float*)mask)[idx] != 0.f;
}

// ---------------- precompute kernels ----------------
__global__ void prep_bias2(const float* __restrict__ lvl, const float* __restrict__ camemb,
                           const float* __restrict__ Wv, const float* __restrict__ bv) {
    int c = blockIdx.x, j = threadIdx.x;
    __shared__ float e[DIM];
    e[j] = lvl[j] + camemb[c*DIM + j];
    __syncthreads();
    const float4* w4 = (const float4*)(Wv + (size_t)j*DIM);
    const float4* e4 = (const float4*)e;
    float s = bv[j];
    #pragma unroll 8
    for (int k = 0; k < DIM/4; k++) {
        float4 w = w4[k]; float4 ev = e4[k];
        s += w.x*ev.x + w.y*ev.y + w.z*ev.z + w.w*ev.w;
    }
    d_bias2[c*DIM + j] = s;
}

__global__ void prep_wc(const float* __restrict__ Wo, const float* __restrict__ Wi) {
    int i = blockIdx.x, j = threadIdx.x;
    __shared__ float wo[DIM];
    wo[j] = Wo[(size_t)i*DIM + j];
    __syncthreads();
    float s = 0.f;
    #pragma unroll 8
    for (int k = 0; k < DIM; k++) s += wo[k] * Wi[(size_t)k*DIM + j];
    d_Wc[(size_t)i*DIM + j] = s;
}

__global__ void prep_bi2(const float* __restrict__ Wo, const float* __restrict__ bi) {
    int w = threadIdx.x >> 5, l = threadIdx.x & 31;
    int i = blockIdx.x*8 + w;
    float s = 0.f;
    #pragma unroll
    for (int t = 0; t < 8; t++) {
        int k = l + 32*t;
        s += Wo[(size_t)i*DIM + k] * bi[k];
    }
    #pragma unroll
    for (int o = 16; o; o >>= 1) s += __shfl_xor_sync(0xffffffffu, s, o);
    if (l == 0) d_bi2[i] = s;
}

// ---------------- unified FFMA2 GEMM core ----------------
// C[M x 64-tile] = A[M x 256] @ B^T, tiles BM=256 x BN=64 x BK=16, 256 thr, thread 16x4
// MODE 1: value GEMM   (A = feat k-major, C -> d_value w/ head remap + bias2)
// MODE 2: offattn GEMM (A = qry+pos, B = [Woff;Wattn], C -> d_offattn + bias)
// MODE 3: final GEMM   (A = d_S, B = d_Wc, C -> out + b_out + g*bi2)
template<int MODE>
__global__ __launch_bounds__(256, 2) void gemm_core(
    const float* __restrict__ A0, const float* __restrict__ A1,
    const float* __restrict__ B0, const float* __restrict__ B1,
    const float* __restrict__ bias0, const float* __restrict__ bias1,
    float* __restrict__ C)
{
    __shared__ float As[BK][ASTR];
    __shared__ float Bs2[BK][BSTR];
    const int tid = threadIdx.x;
    const int ty = tid >> 4, tx = tid & 15;
    const int bn = blockIdx.x, bm = blockIdx.y;
    const int j0 = bn*BN;

    int camI = 0, p0 = 0, m0 = 0;
    if (MODE == 1) { camI = bm/11; p0 = (bm%11)*256; }
    else m0 = bm*BM;
    const int Mrows = (MODE == 2) ? MROWS : QN;

    const float* Aptr = (MODE == 3) ? (const float*)d_S : A0;
    const float* Brow;
    if (MODE == 2) Brow = (j0 < 128) ? (B0 + (size_t)j0*DIM) : (B1 + (size_t)(j0-128)*DIM);
    else if (MODE == 3) Brow = (const float*)d_Wc + (size_t)j0*DIM;
    else Brow = B0 + (size_t)j0*DIM;

    unsigned long long acc[8][4];
    #pragma unroll
    for (int p = 0; p < 8; p++)
        #pragma unroll
        for (int j = 0; j < 4; j++) acc[p][j] = 0ull;

    const int lkq = tid & 3, lm = tid >> 2;    // MODE 2/3 A-load
    const int kk = tid & 15, qd = tid >> 4;    // MODE 1 A-load
    const int bj = tid >> 2, bkq = tid & 3;    // B load

    for (int k0 = 0; k0 < DIM; k0 += BK) {
        if (MODE == 1) {
            const float* fb = Aptr + ((size_t)(camI*DIM) + k0 + kk)*HWF + p0;
            #pragma unroll
            for (int i = 0; i < 4; i++) {
                float4 v = *(const float4*)(fb + (qd + 16*i)*4);
                *(float4*)&As[kk][(qd + 16*i)*4] = v;
            }
        } else {
            #pragma unroll
            for (int i = 0; i < 4; i++) {
                int ml = lm + 64*i;
                int m = m0 + ml;
                float4 va = make_float4(0.f, 0.f, 0.f, 0.f);
                if (m < Mrows) {
                    va = *(const float4*)(Aptr + (size_t)m*DIM + k0 + lkq*4);
                    if (MODE == 2) {
                        float4 vp = *(const float4*)(A1 + (size_t)m*DIM + k0 + lkq*4);
                        va.x += vp.x; va.y += vp.y; va.z += vp.z; va.w += vp.w;
                    }
                }
                As[lkq*4+0][ml] = va.x; As[lkq*4+1][ml] = va.y;
                As[lkq*4+2][ml] = va.z; As[lkq*4+3][ml] = va.w;
            }
        }
        {
            float4 v = *(const float4*)(Brow + (size_t)bj*DIM + k0 + bkq*4);
            *(float2*)&Bs2[bkq*4+0][2*bj] = make_float2(v.x, v.x);
            *(float2*)&Bs2[bkq*4+1][2*bj] = make_float2(v.y, v.y);
            *(float2*)&Bs2[bkq*4+2][2*bj] = make_float2(v.z, v.z);
            *(float2*)&Bs2[bkq*4+3][2*bj] = make_float2(v.w, v.w);
        }
        __syncthreads();
        #pragma unroll
        for (int k = 0; k < BK; k++) {
            ulonglong2 a01 = *(const ulonglong2*)&As[k][ty*16];
            ulonglong2 a23 = *(const ulonglong2*)&As[k][ty*16 + 4];
            ulonglong2 a45 = *(const ulonglong2*)&As[k][ty*16 + 8];
            ulonglong2 a67 = *(const ulonglong2*)&As[k][ty*16 + 12];
            ulonglong2 b01 = *(const ulonglong2*)&Bs2[k][tx*8];
            ulonglong2 b23 = *(const ulonglong2*)&Bs2[k][tx*8 + 4];
            unsigned long long av[8] = {a01.x, a01.y, a23.x, a23.y, a45.x, a45.y, a67.x, a67.y};
            unsigned long long bv[4] = {b01.x, b01.y, b23.x, b23.y};
            #pragma unroll
            for (int p = 0; p < 8; p++)
                #pragma unroll
                for (int j = 0; j < 4; j++) ffma2(acc[p][j], av[p], bv[j]);
        }
        __syncthreads();
    }

    const int jb = j0 + tx*4;
    if (MODE == 1) {
        int h = jb >> 5, hd = jb & 31;
        float4 b2 = *(const float4*)&d_bias2[camI*DIM + jb];
        float* vout = d_value + (size_t)(camI*NH + h)*HWF*HD + hd;
        #pragma unroll
        for (int p = 0; p < 8; p++) {
            float2 u0 = u2f(acc[p][0]), u1 = u2f(acc[p][1]);
            float2 u2 = u2f(acc[p][2]), u3 = u2f(acc[p][3]);
            int pr = p0 + ty*16 + 2*p;
            *(float4*)(vout + (size_t)pr*HD) =
                make_float4(u0.x + b2.x, u1.x + b2.y, u2.x + b2.z, u3.x + b2.w);
            *(float4*)(vout + (size_t)(pr+1)*HD) =
                make_float4(u0.y + b2.x, u1.y + b2.y, u2.y + b2.z, u3.y + b2.w);
        }
    } else if (MODE == 2) {
        const float* bp = (jb < 128) ? (bias0 + jb) : (bias1 + (jb - 128));
        float4 bias = *(const float4*)bp;
        #pragma unroll
        for (int p = 0; p < 8; p++) {
            float2 u0 = u2f(acc[p][0]), u1 = u2f(acc[p][1]);
            float2 u2 = u2f(acc[p][2]), u3 = u2f(acc[p][3]);
            int m = m0 + ty*16 + 2*p;
            if (m < MROWS)
                *(float4*)&d_offattn[(size_t)m*OAC + jb] =
                    make_float4(u0.x + bias.x, u1.x + bias.y, u2.x + bias.z, u3.x + bias.w);
            if (m + 1 < MROWS)
                *(float4*)&d_offattn[(size_t)(m+1)*OAC + jb] =
                    make_float4(u0.y + bias.x, u1.y + bias.y, u2.y + bias.z, u3.y + bias.w);
        }
    } else {
        float4 bo  = *(const float4*)&bias0[jb];
        float4 bi2 = *(const float4*)&d_bi2[jb];
        #pragma unroll
        for (int p = 0; p < 8; p++) {
            float2 u0 = u2f(acc[p][0]), u1 = u2f(acc[p][1]);
            float2 u2 = u2f(acc[p][2]), u3 = u2f(acc[p][3]);
            int m = m0 + ty*16 + 2*p;
            if (m < QN) {
                float g = d_gflag[m];
                *(float4*)&C[(size_t)m*DIM + jb] =
                    make_float4(u0.x + bo.x + g*bi2.x, u1.x + bo.y + g*bi2.y,
                                u2.x + bo.z + g*bi2.z, u3.x + bo.w + g*bi2.w);
            }
            if (m + 1 < QN) {
                float g = d_gflag[m+1];
                *(float4*)&C[(size_t)(m+1)*DIM + jb] =
                    make_float4(u0.y + bo.x + g*bi2.x, u1.y + bo.y + g*bi2.y,
                                u2.y + bo.z + g*bi2.z, u3.y + bo.w + g*bi2.w);
            }
        }
    }
}

// ---------------- sampling + softmax + camera reduction ----------------
__global__ __launch_bounds__(256) void sample_kernel(const float* __restrict__ ref,
                                                     const void* __restrict__ mask) {
    const int q = blockIdx.x;
    const int tid = threadIdx.x;
    const int h = tid>>5, l = tid&31;
    const int corner = l>>3, c8 = l&7;
    const int ox = corner&1, oy = corner>>1;
    __shared__ float s_hit[NCAM];
    __shared__ float s_inv, s_g;
    if (tid < NCAM) {
        const int mode = d_mask_mode;
        size_t base = (size_t)(tid*QN + q)*8;
        int hit = mask_elem(mask, base+0, mode) | mask_elem(mask, base+2, mode) |
                  mask_elem(mask, base+4, mode) | mask_elem(mask, base+6, mode);
        s_hit[tid] = hit ? 1.f : 0.f;
    }
    __syncthreads();
    if (tid == 0) {
        float c = s_hit[0]+s_hit[1]+s_hit[2]+s_hit[3]+s_hit[4]+s_hit[5];
        s_g = (c > 0.f) ? 1.f : 0.f;
        s_inv = 1.f / fmaxf(c, 1.f);
    }
    __syncthreads();
    float ax=0.f, ay=0.f, az=0.f, aw=0.f;
    for (int camI = 0; camI < NCAM; camI++) {
        if (s_hit[camI] == 0.f) continue;
        const float* row = d_offattn + (size_t)(camI*QN + q)*OAC;
        float logit = row[128 + h*8 + c8];
        float ofx   = row[h*16 + c8*2];
        float ofy   = row[h*16 + c8*2 + 1];
        const float* rp = ref + ((size_t)(camI*QN + q)*4 + (c8&3))*2;
        float rx = rp[0], ry = rp[1];
        float mx = logit;
        mx = fmaxf(mx, __shfl_xor_sync(0xffffffffu, mx, 1, 8));
        mx = fmaxf(mx, __shfl_xor_sync(0xffffffffu, mx, 2, 8));
        mx = fmaxf(mx, __shfl_xor_sync(0xffffffffu, mx, 4, 8));
        float e = __expf(logit - mx);
        float sm = e;
        sm += __shfl_xor_sync(0xffffffffu, sm, 1, 8);
        sm += __shfl_xor_sync(0xffffffffu, sm, 2, 8);
        sm += __shfl_xor_sync(0xffffffffu, sm, 4, 8);
        float w = e / sm;
        const float* vb = d_value + (size_t)(camI*NH + h)*HWF*HD + c8*4;
        #pragma unroll
        for (int p = 0; p < 8; p++) {
            float wp  = __shfl_sync(0xffffffffu, w,   p, 8);
            float fx  = __shfl_sync(0xffffffffu, ofx, p, 8);
            float fy  = __shfl_sync(0xffffffffu, ofy, p, 8);
            float rxp = __shfl_sync(0xffffffffu, rx,  p, 8);
            float ryp = __shfl_sync(0xffffffffu, ry,  p, 8);
            float x = fmaf(rxp, (float)WFv, fx) - 0.5f;
            float y = fmaf(ryp, (float)HFv, fy) - 0.5f;
            float xf = floorf(x), yf = floorf(y);
            float dx = x - xf, dy = y - yf;
            int xi = (int)xf + ox;
            int yi = (int)yf + oy;
            float wx = ox ? dx : (1.f - dx);
            float wy = oy ? dy : (1.f - dy);
            bool valid = (xi >= 0) && (xi < WFv) && (yi >= 0) && (yi < HFv);
            float wc = valid ? (wp*wx*wy) : 0.f;
            int pix = min(max(yi,0),HFv-1)*WFv + min(max(xi,0),WFv-1);
            float4 v = *(const float4*)(vb + (size_t)pix*HD);
            ax = fmaf(wc, v.x, ax); ay = fmaf(wc, v.y, ay);
            az = fmaf(wc, v.z, az); aw = fmaf(wc, v.w, aw);
        }
    }
    ax += __shfl_xor_sync(0xffffffffu, ax, 8);  ax += __shfl_xor_sync(0xffffffffu, ax, 16);
    ay += __shfl_xor_sync(0xffffffffu, ay, 8);  ay += __shfl_xor_sync(0xffffffffu, ay, 16);
    az += __shfl_xor_sync(0xffffffffu, az, 8);  az += __shfl_xor_sync(0xffffffffu, az, 16);
    aw += __shfl_xor_sync(0xffffffffu, aw, 8);  aw += __shfl_xor_sync(0xffffffffu, aw, 16);
    if (l < 8) {
        float inv = s_inv;
        float4 o = make_float4(ax*inv, ay*inv, az*inv, aw*inv);
        *(float4*)&d_S[(size_t)q*DIM + h*HD + c8*4] = o;
    }
    if (tid == 0) d_gflag[q] = s_g;
}

// ---------------- launch ----------------
extern "C" void kernel_launch(void* const* d_in, const int* in_sizes, int n_in,
                              void* d_out, int out_size) {
    const float* queries = (const float*)d_in[0];
    const float* pos     = (const float*)d_in[1];
    const float* lvl     = (const float*)d_in[2];
    const float* camemb  = (const float*)d_in[3];
    const float* feat    = (const float*)d_in[4];
    const float* ref     = (const float*)d_in[5];
    const void*  mask    = (const void*)d_in[6];
    const float* W_value = (const float*)d_in[7];
    const float* W_off   = (const float*)d_in[9];
    const float* b_off   = (const float*)d_in[10];
    const float* W_attn  = (const float*)d_in[11];
    const float* b_attn  = (const float*)d_in[12];
    const float* W_inner = (const float*)d_in[13];
    const float* b_inner = (const float*)d_in[14];
    const float* W_out   = (const float*)d_in[15];
    const float* b_out   = (const float*)d_in[16];
    const float* b_value = (const float*)d_in[8];
    float* out = (float*)d_out;

    detect_mask<<<1, 32>>>((const unsigned int*)mask);
    prep_bias2<<<NCAM, DIM>>>(lvl, camemb, W_value, b_value);
    prep_wc<<<DIM, DIM>>>(W_out, W_inner);
    prep_bi2<<<32, 256>>>(W_out, b_inner);
    gemm_core<1><<<dim3(4, 66), 256>>>(feat, nullptr, W_value, nullptr,
                                       nullptr, nullptr, nullptr);
    gemm_core<2><<<dim3(3, 235), 256>>>(queries, pos, W_off, W_attn,
                                        b_off, b_attn, nullptr);
    sample_kernel<<<QN, 256>>>(ref, mask);
    gemm_core<3><<<dim3(4, 40), 256>>>(nullptr, nullptr, nullptr, nullptr,
                                       b_out, nullptr, out);
    (void)in_sizes; (void)n_in; (void)out_size; (void)W_inner; (void)b_inner;
}

// round 5
// speedup vs baseline: 1.4164x; 1.4164x over previous
#include <cuda_runtime.h>
#include <cstdint>

#define QN   10000
#define NCAM 6
#define DIM  256
#define HWF  2816     // 32*88
#define NH   8
#define HD   32
#define HFv  32
#define WFv  88
#define MROWS (NCAM*QN)   // 60000
#define OAC  192          // 128 offsets + 64 attn logits

// ---------------- scratch ----------------
__device__ float d_value[NCAM*NH*HWF*HD];   // (cam, head, hw, hd)
__device__ float d_offattn[(size_t)MROWS*OAC];
__device__ float d_S[(size_t)QN*DIM];
__device__ float d_gflag[QN];
__device__ float d_bias2[NCAM*DIM];
__device__ float d_Wc[DIM*DIM];             // W_out @ W_inner
__device__ float d_bi2[DIM];                // W_out @ b_inner
__device__ int   d_mask_mode;               // 0=u8, 1=i32, 2=f32

__device__ __forceinline__ int mask_elem(const void* mask, size_t idx, int mode) {
    if (mode == 0) return ((const unsigned char*)mask)[idx] != 0;
    if (mode == 1) return ((const int*)mask)[idx] != 0;
    return ((const float*)mask)[idx] != 0.f;
}

// ---------------- prep A: bias2 (blocks 0..5) + mask detect (block 6) ----------------
__global__ void prep_a(const float* __restrict__ lvl, const float* __restrict__ camemb,
                       const float* __restrict__ Wv, const float* __restrict__ bv,
                       const unsigned int* __restrict__ mk) {
    int c = blockIdx.x, j = threadIdx.x;
    if (c == NCAM) {
        if (j < 32) {
            bool f = false, multi = false;
            for (int i = j; i < 256; i += 32) {
                unsigned int w = mk[i];
                f |= (w == 0x3F800000u);
                multi |= (w != 0x3F800000u && w > 1u);
            }
            unsigned bf = __ballot_sync(0xffffffffu, f), bm = __ballot_sync(0xffffffffu, multi);
            if (j == 0) d_mask_mode = bf ? 2 : (bm ? 0 : 1);
        }
        return;
    }
    __shared__ float e[DIM];
    e[j] = lvl[j] + camemb[c*DIM + j];
    __syncthreads();
    const float4* w4 = (const float4*)(Wv + (size_t)j*DIM);
    const float4* e4 = (const float4*)e;
    float s = bv[j];
    #pragma unroll 8
    for (int k = 0; k < DIM/4; k++) {
        float4 w = w4[k]; float4 ev = e4[k];
        s += w.x*ev.x + w.y*ev.y + w.z*ev.z + w.w*ev.w;
    }
    d_bias2[c*DIM + j] = s;
}

// ---------------- prep B: Wc (blocks 0..255) + bi2 (block 256) ----------------
__global__ void prep_b(const float* __restrict__ Wo, const float* __restrict__ Wi,
                       const float* __restrict__ bi) {
    int i = blockIdx.x, j = threadIdx.x;
    if (i == DIM) {
        int w = j >> 5, l = j & 31;
        for (int ii = w; ii < DIM; ii += 8) {
            float s = 0.f;
            #pragma unroll
            for (int t = 0; t < 8; t++) {
                int k = l + 32*t;
                s += Wo[(size_t)ii*DIM + k] * bi[k];
            }
            #pragma unroll
            for (int o = 16; o; o >>= 1) s += __shfl_xor_sync(0xffffffffu, s, o);
            if (l == 0) d_bi2[ii] = s;
        }
        return;
    }
    __shared__ float wo[DIM];
    wo[j] = Wo[(size_t)i*DIM + j];
    __syncthreads();
    float s = 0.f;
    #pragma unroll 8
    for (int k = 0; k < DIM; k++) s += wo[k] * Wi[(size_t)k*DIM + j];
    d_Wc[(size_t)i*DIM + j] = s;
}

// ---------------- tf32 mma.sync GEMM core ----------------
// MODE 1: value (A = feat k-major, 16896x256; C -> d_value + bias2, head remap)
// MODE 2: offattn (A = qry+pos 60000x256, B = [Woff;Wattn] 192; C -> d_offattn + bias)
// MODE 3: final (A = d_S 10000x256, B = d_Wc; C -> out + b_out + g*bi2)
#define ASTR 20
#define ASTR1 136
#define BSTR 20

__device__ __forceinline__ unsigned f2tf(float f) {
    unsigned u; asm("cvt.rna.tf32.f32 %0, %1;" : "=r"(u) : "f"(f)); return u;
}
__device__ __forceinline__ void mma1688(float* c, const unsigned* a, const unsigned* b) {
    asm volatile("mma.sync.aligned.m16n8k8.row.col.f32.tf32.tf32.f32 "
        "{%0,%1,%2,%3}, {%4,%5,%6,%7}, {%8,%9}, {%0,%1,%2,%3};"
        : "+f"(c[0]), "+f"(c[1]), "+f"(c[2]), "+f"(c[3])
        : "r"(a[0]), "r"(a[1]), "r"(a[2]), "r"(a[3]), "r"(b[0]), "r"(b[1]));
}
__device__ __forceinline__ uint4 tf4(float4 v) {
    return make_uint4(f2tf(v.x), f2tf(v.y), f2tf(v.z), f2tf(v.w));
}

template<int MODE>
__global__ __launch_bounds__(256, 2) void gemm_tc(
    const float* __restrict__ A0, const float* __restrict__ A1,
    const float* __restrict__ B0, const float* __restrict__ B1,
    const float* __restrict__ bias0, const float* __restrict__ bias1,
    float* __restrict__ C)
{
    __shared__ unsigned As[2][2560];
    __shared__ unsigned Bs[2][1280];
    const int tid = threadIdx.x;
    const int lane = tid & 31, wid = tid >> 5;
    const int mw = (wid & 3) * 32, nw = (wid >> 2) * 32;
    const int g = lane >> 2, t = lane & 3;
    const int j0 = blockIdx.x * 64;

    int camI = 0, p0 = 0, m0 = 0;
    if (MODE == 1) { camI = blockIdx.y / 22; p0 = (blockIdx.y % 22) * 128; }
    else m0 = blockIdx.y * 128;
    const int Mrows = (MODE == 2) ? MROWS : QN;

    const float* Aptr = (MODE == 3) ? (const float*)d_S : A0;
    // B row pointer per thread (row = j0 + (tid>>2))
    const int bn_ = tid >> 2, bkq = (tid & 3) * 4;
    const int jg = j0 + bn_;
    const float* wrow;
    if (MODE == 2) wrow = (jg < 128) ? (B0 + (size_t)jg*DIM) : (B1 + (size_t)(jg-128)*DIM);
    else if (MODE == 3) wrow = (const float*)d_Wc + (size_t)jg*DIM;
    else wrow = B0 + (size_t)jg*DIM;

    // A staging indices
    const int am = tid >> 1, akq = (tid & 1) * 8;       // MODE 2/3
    const int kk = tid >> 4, pg = tid & 15;             // MODE 1
    const int mga = m0 + am;

    float c_[2][4][4];
    #pragma unroll
    for (int mi = 0; mi < 2; mi++)
        #pragma unroll
        for (int ni = 0; ni < 4; ni++)
            #pragma unroll
            for (int r = 0; r < 4; r++) c_[mi][ni][r] = 0.f;

    float4 pa0, pa1, pb;

    // ---- load chunk k0 into regs ----
    auto zero4 = make_float4(0.f, 0.f, 0.f, 0.f);
    #define LOAD_CHUNK(k0) do {                                                      \
        if (MODE == 1) {                                                             \
            const float* src = A0 + ((size_t)(camI*DIM + (k0) + kk))*HWF + p0 + pg*8;\
            pa0 = *(const float4*)src; pa1 = *(const float4*)(src + 4);              \
        } else {                                                                     \
            pa0 = zero4; pa1 = zero4;                                                \
            if (mga < Mrows) {                                                       \
                pa0 = *(const float4*)(Aptr + (size_t)mga*DIM + (k0) + akq);         \
                pa1 = *(const float4*)(Aptr + (size_t)mga*DIM + (k0) + akq + 4);     \
                if (MODE == 2) {                                                     \
                    float4 q0 = *(const float4*)(A1 + (size_t)mga*DIM + (k0) + akq); \
                    float4 q1 = *(const float4*)(A1 + (size_t)mga*DIM + (k0) + akq+4);\
                    pa0.x+=q0.x; pa0.y+=q0.y; pa0.z+=q0.z; pa0.w+=q0.w;              \
                    pa1.x+=q1.x; pa1.y+=q1.y; pa1.z+=q1.z; pa1.w+=q1.w;              \
                }                                                                    \
            }                                                                        \
        }                                                                            \
        pb = *(const float4*)(wrow + (k0) + bkq);                                    \
    } while (0)

    #define STORE_CHUNK(buf) do {                                                   \
        if (MODE == 1) {                                                            \
            *(uint4*)&As[buf][kk*ASTR1 + pg*8]     = tf4(pa0);                      \
            *(uint4*)&As[buf][kk*ASTR1 + pg*8 + 4] = tf4(pa1);                      \
        } else {                                                                    \
            *(uint4*)&As[buf][am*ASTR + akq]     = tf4(pa0);                        \
            *(uint4*)&As[buf][am*ASTR + akq + 4] = tf4(pa1);                        \
        }                                                                           \
        *(uint4*)&Bs[buf][bn_*BSTR + bkq] = tf4(pb);                                \
    } while (0)

    LOAD_CHUNK(0);
    STORE_CHUNK(0);
    __syncthreads();

    #pragma unroll 1
    for (int cch = 0; cch < 16; cch++) {
        const int buf = cch & 1;
        if (cch < 15) LOAD_CHUNK((cch + 1) * 16);
        const unsigned* Ab = As[buf];
        const unsigned* Bb = Bs[buf];
        #pragma unroll
        for (int ks = 0; ks < 2; ks++) {
            const int k8 = ks * 8;
            unsigned a[2][4], b[4][2];
            #pragma unroll
            for (int mi = 0; mi < 2; mi++) {
                int mr = mw + mi*16 + g;
                if (MODE == 1) {
                    a[mi][0] = Ab[(k8 + t)*ASTR1 + mr];
                    a[mi][1] = Ab[(k8 + t)*ASTR1 + mr + 8];
                    a[mi][2] = Ab[(k8 + t + 4)*ASTR1 + mr];
                    a[mi][3] = Ab[(k8 + t + 4)*ASTR1 + mr + 8];
                } else {
                    a[mi][0] = Ab[mr*ASTR + k8 + t];
                    a[mi][1] = Ab[(mr + 8)*ASTR + k8 + t];
                    a[mi][2] = Ab[mr*ASTR + k8 + t + 4];
                    a[mi][3] = Ab[(mr + 8)*ASTR + k8 + t + 4];
                }
            }
            #pragma unroll
            for (int ni = 0; ni < 4; ni++) {
                int nr = nw + ni*8 + g;
                b[ni][0] = Bb[nr*BSTR + k8 + t];
                b[ni][1] = Bb[nr*BSTR + k8 + t + 4];
            }
            #pragma unroll
            for (int mi = 0; mi < 2; mi++)
                #pragma unroll
                for (int ni = 0; ni < 4; ni++)
                    mma1688(c_[mi][ni], a[mi], b[ni]);
        }
        if (cch < 15) STORE_CHUNK(buf ^ 1);
        __syncthreads();
    }

    // ---- epilogue ----
    #pragma unroll
    for (int mi = 0; mi < 2; mi++) {
        #pragma unroll
        for (int ni = 0; ni < 4; ni++) {
            const int jc = j0 + nw + ni*8 + 2*t;
            const int r0 = mw + mi*16 + g;
            const float* cr = c_[mi][ni];
            if (MODE == 1) {
                const int h = jc >> 5, hd = jc & 31;
                float b0 = d_bias2[camI*DIM + jc], b1 = d_bias2[camI*DIM + jc + 1];
                float* o0 = d_value + ((size_t)(camI*NH + h)*HWF + p0 + r0)*HD + hd;
                float* o1 = o0 + 8*HD;
                *(float2*)o0 = make_float2(cr[0] + b0, cr[1] + b1);
                *(float2*)o1 = make_float2(cr[2] + b0, cr[3] + b1);
            } else if (MODE == 2) {
                float b0, b1;
                if (jc < 128) { b0 = bias0[jc]; b1 = bias0[jc+1]; }
                else          { b0 = bias1[jc-128]; b1 = bias1[jc-127]; }
                int mr0 = m0 + r0, mr1 = mr0 + 8;
                if (mr0 < MROWS)
                    *(float2*)&d_offattn[(size_t)mr0*OAC + jc] = make_float2(cr[0]+b0, cr[1]+b1);
                if (mr1 < MROWS)
                    *(float2*)&d_offattn[(size_t)mr1*OAC + jc] = make_float2(cr[2]+b0, cr[3]+b1);
            } else {
                float b0 = bias0[jc] , b1 = bias0[jc+1];
                float e0 = d_bi2[jc], e1 = d_bi2[jc+1];
                int mr0 = m0 + r0, mr1 = mr0 + 8;
                if (mr0 < QN) {
                    float gf = d_gflag[mr0];
                    *(float2*)&C[(size_t)mr0*DIM + jc] =
                        make_float2(cr[0] + b0 + gf*e0, cr[1] + b1 + gf*e1);
                }
                if (mr1 < QN) {
                    float gf = d_gflag[mr1];
                    *(float2*)&C[(size_t)mr1*DIM + jc] =
                        make_float2(cr[2] + b0 + gf*e0, cr[3] + b1 + gf*e1);
                }
            }
        }
    }
    #undef LOAD_CHUNK
    #undef STORE_CHUNK
}

// ---------------- sampling + softmax + camera reduction ----------------
__global__ __launch_bounds__(256) void sample_kernel(const float* __restrict__ ref,
                                                     const void* __restrict__ mask) {
    const int q = blockIdx.x;
    const int tid = threadIdx.x;
    const int h = tid>>5, l = tid&31;
    const int corner = l>>3, c8 = l&7;
    const int ox = corner&1, oy = corner>>1;
    __shared__ float s_hit[NCAM];
    __shared__ float s_inv, s_g;
    if (tid < NCAM) {
        const int mode = d_mask_mode;
        size_t base = (size_t)(tid*QN + q)*8;
        int hit = mask_elem(mask, base+0, mode) | mask_elem(mask, base+2, mode) |
                  mask_elem(mask, base+4, mode) | mask_elem(mask, base+6, mode);
        s_hit[tid] = hit ? 1.f : 0.f;
    }
    __syncthreads();
    if (tid == 0) {
        float c = s_hit[0]+s_hit[1]+s_hit[2]+s_hit[3]+s_hit[4]+s_hit[5];
        s_g = (c > 0.f) ? 1.f : 0.f;
        s_inv = 1.f / fmaxf(c, 1.f);
    }
    __syncthreads();
    float ax=0.f, ay=0.f, az=0.f, aw=0.f;
    for (int camI = 0; camI < NCAM; camI++) {
        if (s_hit[camI] == 0.f) continue;
        const float* row = d_offattn + (size_t)(camI*QN + q)*OAC;
        float logit = row[128 + h*8 + c8];
        float ofx   = row[h*16 + c8*2];
        float ofy   = row[h*16 + c8*2 + 1];
        const float* rp = ref + ((size_t)(camI*QN + q)*4 + (c8&3))*2;
        float rx = rp[0], ry = rp[1];
        float mx = logit;
        mx = fmaxf(mx, __shfl_xor_sync(0xffffffffu, mx, 1, 8));
        mx = fmaxf(mx, __shfl_xor_sync(0xffffffffu, mx, 2, 8));
        mx = fmaxf(mx, __shfl_xor_sync(0xffffffffu, mx, 4, 8));
        float e = __expf(logit - mx);
        float sm = e;
        sm += __shfl_xor_sync(0xffffffffu, sm, 1, 8);
        sm += __shfl_xor_sync(0xffffffffu, sm, 2, 8);
        sm += __shfl_xor_sync(0xffffffffu, sm, 4, 8);
        float w = e / sm;
        const float* vb = d_value + (size_t)(camI*NH + h)*HWF*HD + c8*4;
        #pragma unroll
        for (int p = 0; p < 8; p++) {
            float wp  = __shfl_sync(0xffffffffu, w,   p, 8);
            float fx  = __shfl_sync(0xffffffffu, ofx, p, 8);
            float fy  = __shfl_sync(0xffffffffu, ofy, p, 8);
            float rxp = __shfl_sync(0xffffffffu, rx,  p, 8);
            float ryp = __shfl_sync(0xffffffffu, ry,  p, 8);
            float x = fmaf(rxp, (float)WFv, fx) - 0.5f;
            float y = fmaf(ryp, (float)HFv, fy) - 0.5f;
            float xf = floorf(x), yf = floorf(y);
            float dx = x - xf, dy = y - yf;
            int xi = (int)xf + ox;
            int yi = (int)yf + oy;
            float wx = ox ? dx : (1.f - dx);
            float wy = oy ? dy : (1.f - dy);
            bool valid = (xi >= 0) && (xi < WFv) && (yi >= 0) && (yi < HFv);
            float wc = valid ? (wp*wx*wy) : 0.f;
            int pix = min(max(yi,0),HFv-1)*WFv + min(max(xi,0),WFv-1);
            float4 v = *(const float4*)(vb + (size_t)pix*HD);
            ax = fmaf(wc, v.x, ax); ay = fmaf(wc, v.y, ay);
            az = fmaf(wc, v.z, az); aw = fmaf(wc, v.w, aw);
        }
    }
    ax += __shfl_xor_sync(0xffffffffu, ax, 8);  ax += __shfl_xor_sync(0xffffffffu, ax, 16);
    ay += __shfl_xor_sync(0xffffffffu, ay, 8);  ay += __shfl_xor_sync(0xffffffffu, ay, 16);
    az += __shfl_xor_sync(0xffffffffu, az, 8);  az += __shfl_xor_sync(0xffffffffu, az, 16);
    aw += __shfl_xor_sync(0xffffffffu, aw, 8);  aw += __shfl_xor_sync(0xffffffffu, aw, 16);
    if (l < 8) {
        float inv = s_inv;
        float4 o = make_float4(ax*inv, ay*inv, az*inv, aw*inv);
        *(float4*)&d_S[(size_t)q*DIM + h*HD + c8*4] = o;
    }
    if (tid == 0) d_gflag[q] = s_g;
}

// ---------------- launch ----------------
extern "C" void kernel_launch(void* const* d_in, const int* in_sizes, int n_in,
                              void* d_out, int out_size) {
    const float* queries = (const float*)d_in[0];
    const float* pos     = (const float*)d_in[1];
    const float* lvl     = (const float*)d_in[2];
    const float* camemb  = (const float*)d_in[3];
    const float* feat    = (const float*)d_in[4];
    const float* ref     = (const float*)d_in[5];
    const void*  mask    = (const void*)d_in[6];
    const float* W_value = (const float*)d_in[7];
    const float* b_value = (const float*)d_in[8];
    const float* W_off   = (const float*)d_in[9];
    const float* b_off   = (const float*)d_in[10];
    const float* W_attn  = (const float*)d_in[11];
    const float* b_attn  = (const float*)d_in[12];
    const float* W_inner = (const float*)d_in[13];
    const float* b_inner = (const float*)d_in[14];
    const float* W_out   = (const float*)d_in[15];
    const float* b_out   = (const float*)d_in[16];
    float* out = (float*)d_out;

    prep_a<<<NCAM + 1, DIM>>>(lvl, camemb, W_value, b_value, (const unsigned int*)mask);
    prep_b<<<DIM + 1, DIM>>>(W_out, W_inner, b_inner);
    gemm_tc<1><<<dim3(4, 132), 256>>>(feat, nullptr, W_value, nullptr,
                                      nullptr, nullptr, nullptr);
    gemm_tc<2><<<dim3(3, 469), 256>>>(queries, pos, W_off, W_attn,
                                      b_off, b_attn, nullptr);
    sample_kernel<<<QN, 256>>>(ref, mask);
    gemm_tc<3><<<dim3(4, 79), 256>>>(nullptr, nullptr, nullptr, nullptr,
                                     b_out, nullptr, out);
    (void)in_sizes; (void)n_in; (void)out_size;
}

// round 6
// speedup vs baseline: 1.4630x; 1.0329x over previous
#include <cuda_runtime.h>
#include <cstdint>

#define QN   10000
#define NCAM 6
#define DIM  256
#define HWF  2816     // 32*88
#define NH   8
#define HD   32
#define HFv  32
#define WFv  88
#define MROWS (NCAM*QN)   // 60000
#define OAC  192          // 128 offsets + 64 attn logits

// ---------------- scratch ----------------
__device__ float d_value[NCAM*NH*HWF*HD];   // (cam, head, hw, hd)
__device__ float d_offattn[(size_t)MROWS*OAC];
__device__ float d_S[(size_t)QN*DIM];
__device__ float d_gflag[QN];
__device__ float d_bias2[NCAM*DIM];
__device__ float d_Wc[DIM*DIM];             // W_out @ W_inner
__device__ float d_bi2[DIM];                // W_out @ b_inner
__device__ int   d_mask_mode;               // 0=u8, 1=i32, 2=f32

__device__ __forceinline__ int mask_elem(const void* mask, size_t idx, int mode) {
    if (mode == 0) return ((const unsigned char*)mask)[idx] != 0;
    if (mode == 1) return ((const int*)mask)[idx] != 0;
    return ((const float*)mask)[idx] != 0.f;
}

// ---------------- prep A: bias2 (blocks 0..5) + mask detect (block 6) ----------------
__global__ void prep_a(const float* __restrict__ lvl, const float* __restrict__ camemb,
                       const float* __restrict__ Wv, const float* __restrict__ bv,
                       const unsigned int* __restrict__ mk) {
    int c = blockIdx.x, j = threadIdx.x;
    if (c == NCAM) {
        if (j < 32) {
            bool f = false, multi = false;
            for (int i = j; i < 256; i += 32) {
                unsigned int w = mk[i];
                f |= (w == 0x3F800000u);
                multi |= (w != 0x3F800000u && w > 1u);
            }
            unsigned bf = __ballot_sync(0xffffffffu, f), bm = __ballot_sync(0xffffffffu, multi);
            if (j == 0) d_mask_mode = bf ? 2 : (bm ? 0 : 1);
        }
        return;
    }
    __shared__ float e[DIM];
    e[j] = lvl[j] + camemb[c*DIM + j];
    __syncthreads();
    const float4* w4 = (const float4*)(Wv + (size_t)j*DIM);
    const float4* e4 = (const float4*)e;
    float s = bv[j];
    #pragma unroll 8
    for (int k = 0; k < DIM/4; k++) {
        float4 w = w4[k]; float4 ev = e4[k];
        s += w.x*ev.x + w.y*ev.y + w.z*ev.z + w.w*ev.w;
    }
    d_bias2[c*DIM + j] = s;
}

// ---------------- prep B: Wc (blocks 0..255) + bi2 (block 256) ----------------
__global__ void prep_b(const float* __restrict__ Wo, const float* __restrict__ Wi,
                       const float* __restrict__ bi) {
    int i = blockIdx.x, j = threadIdx.x;
    if (i == DIM) {
        int w = j >> 5, l = j & 31;
        for (int ii = w; ii < DIM; ii += 8) {
            float s = 0.f;
            #pragma unroll
            for (int t = 0; t < 8; t++) {
                int k = l + 32*t;
                s += Wo[(size_t)ii*DIM + k] * bi[k];
            }
            #pragma unroll
            for (int o = 16; o; o >>= 1) s += __shfl_xor_sync(0xffffffffu, s, o);
            if (l == 0) d_bi2[ii] = s;
        }
        return;
    }
    __shared__ float wo[DIM];
    wo[j] = Wo[(size_t)i*DIM + j];
    __syncthreads();
    float s = 0.f;
    #pragma unroll 8
    for (int k = 0; k < DIM; k++) s += wo[k] * Wi[(size_t)k*DIM + j];
    d_Wc[(size_t)i*DIM + j] = s;
}

// ---------------- tf32 mma.sync GEMM core (ldmatrix operand fetch) ----------------
#define ASTR 20
#define ASTR1 136
#define BSTR 20

__device__ __forceinline__ unsigned f2tf(float f) {
    unsigned u; asm("cvt.rna.tf32.f32 %0, %1;" : "=r"(u) : "f"(f)); return u;
}
__device__ __forceinline__ void mma1688(float* c, const unsigned* a, const unsigned* b) {
    asm volatile("mma.sync.aligned.m16n8k8.row.col.f32.tf32.tf32.f32 "
        "{%0,%1,%2,%3}, {%4,%5,%6,%7}, {%8,%9}, {%0,%1,%2,%3};"
        : "+f"(c[0]), "+f"(c[1]), "+f"(c[2]), "+f"(c[3])
        : "r"(a[0]), "r"(a[1]), "r"(a[2]), "r"(a[3]), "r"(b[0]), "r"(b[1]));
}
__device__ __forceinline__ uint4 tf4(float4 v) {
    return make_uint4(f2tf(v.x), f2tf(v.y), f2tf(v.z), f2tf(v.w));
}
__device__ __forceinline__ void ldmx4(unsigned* r, unsigned addr) {
    asm volatile("ldmatrix.sync.aligned.m8n8.x4.shared.b16 {%0,%1,%2,%3}, [%4];"
        : "=r"(r[0]), "=r"(r[1]), "=r"(r[2]), "=r"(r[3]) : "r"(addr));
}
__device__ __forceinline__ unsigned smem_addr(const void* p) {
    return (unsigned)__cvta_generic_to_shared(p);
}

template<int MODE>
__global__ __launch_bounds__(256, 2) void gemm_tc(
    const float* __restrict__ A0, const float* __restrict__ A1,
    const float* __restrict__ B0, const float* __restrict__ B1,
    const float* __restrict__ bias0, const float* __restrict__ bias1,
    float* __restrict__ C)
{
    __shared__ unsigned As[2][2560];
    __shared__ unsigned Bs[2][1280];
    const int tid = threadIdx.x;
    const int lane = tid & 31, wid = tid >> 5;
    const int mw = (wid & 3) * 32, nw = (wid >> 2) * 32;
    const int g = lane >> 2, t = lane & 3;
    const int j0 = blockIdx.x * 64;

    int camI = 0, p0 = 0, m0 = 0;
    if (MODE == 1) { camI = blockIdx.y / 22; p0 = (blockIdx.y % 22) * 128; }
    else m0 = blockIdx.y * 128;
    const int Mrows = (MODE == 2) ? MROWS : QN;

    const float* Aptr = (MODE == 3) ? (const float*)d_S : A0;
    const int bn_ = tid >> 2, bkq = (tid & 3) * 4;
    const int jg = j0 + bn_;
    const float* wrow;
    if (MODE == 2) wrow = (jg < 128) ? (B0 + (size_t)jg*DIM) : (B1 + (size_t)(jg-128)*DIM);
    else if (MODE == 3) wrow = (const float*)d_Wc + (size_t)jg*DIM;
    else wrow = B0 + (size_t)jg*DIM;

    const int am = tid >> 1, akq = (tid & 1) * 8;       // MODE 2/3 A staging
    const int kk = tid >> 4, pg = tid & 15;             // MODE 1 A staging
    const int mga = m0 + am;

    // ldmatrix per-lane addresses
    const unsigned as_base = smem_addr(&As[0][0]);
    const unsigned bs_base = smem_addr(&Bs[0][0]);
    const int arow = mw + (lane & 7) + ((lane >> 3) & 1) * 8;
    const int acol = ((lane >> 4) & 1) * 4;
    const int brow = nw + (lane & 7) + ((lane >> 4) & 1) * 8;
    const int bcol = ((lane >> 3) & 1) * 4;

    float c_[2][4][4];
    #pragma unroll
    for (int mi = 0; mi < 2; mi++)
        #pragma unroll
        for (int ni = 0; ni < 4; ni++)
            #pragma unroll
            for (int r = 0; r < 4; r++) c_[mi][ni][r] = 0.f;

    float4 pa0, pa1, pb;
    auto zero4 = make_float4(0.f, 0.f, 0.f, 0.f);
    #define LOAD_CHUNK(k0) do {                                                      \
        if (MODE == 1) {                                                             \
            const float* src = A0 + ((size_t)(camI*DIM + (k0) + kk))*HWF + p0 + pg*8;\
            pa0 = *(const float4*)src; pa1 = *(const float4*)(src + 4);              \
        } else {                                                                     \
            pa0 = zero4; pa1 = zero4;                                                \
            if (mga < Mrows) {                                                       \
                pa0 = *(const float4*)(Aptr + (size_t)mga*DIM + (k0) + akq);         \
                pa1 = *(const float4*)(Aptr + (size_t)mga*DIM + (k0) + akq + 4);     \
                if (MODE == 2) {                                                     \
                    float4 q0 = *(const float4*)(A1 + (size_t)mga*DIM + (k0) + akq); \
                    float4 q1 = *(const float4*)(A1 + (size_t)mga*DIM + (k0) + akq+4);\
                    pa0.x+=q0.x; pa0.y+=q0.y; pa0.z+=q0.z; pa0.w+=q0.w;              \
                    pa1.x+=q1.x; pa1.y+=q1.y; pa1.z+=q1.z; pa1.w+=q1.w;              \
                }                                                                    \
            }                                                                        \
        }                                                                            \
        pb = *(const float4*)(wrow + (k0) + bkq);                                    \
    } while (0)

    #define STORE_CHUNK(buf) do {                                                   \
        if (MODE == 1) {                                                            \
            *(uint4*)&As[buf][kk*ASTR1 + pg*8]     = tf4(pa0);                      \
            *(uint4*)&As[buf][kk*ASTR1 + pg*8 + 4] = tf4(pa1);                      \
        } else {                                                                    \
            *(uint4*)&As[buf][am*ASTR + akq]     = tf4(pa0);                        \
            *(uint4*)&As[buf][am*ASTR + akq + 4] = tf4(pa1);                        \
        }                                                                           \
        *(uint4*)&Bs[buf][bn_*BSTR + bkq] = tf4(pb);                                \
    } while (0)

    LOAD_CHUNK(0);
    STORE_CHUNK(0);
    __syncthreads();

    #pragma unroll 1
    for (int cch = 0; cch < 16; cch++) {
        const int buf = cch & 1;
        if (cch < 15) LOAD_CHUNK((cch + 1) * 16);
        const unsigned* Ab = As[buf];
        const unsigned aoff = as_base + (unsigned)buf * 2560u * 4u;
        const unsigned boff = bs_base + (unsigned)buf * 1280u * 4u;
        #pragma unroll
        for (int ks = 0; ks < 2; ks++) {
            const int k8 = ks * 8;
            unsigned a[2][4], b[2][4];
            if (MODE == 1) {
                #pragma unroll
                for (int mi = 0; mi < 2; mi++) {
                    int mr = mw + mi*16 + g;
                    a[mi][0] = Ab[(k8 + t)*ASTR1 + mr];
                    a[mi][1] = Ab[(k8 + t)*ASTR1 + mr + 8];
                    a[mi][2] = Ab[(k8 + t + 4)*ASTR1 + mr];
                    a[mi][3] = Ab[(k8 + t + 4)*ASTR1 + mr + 8];
                }
            } else {
                #pragma unroll
                for (int mi = 0; mi < 2; mi++)
                    ldmx4(a[mi], aoff + ((unsigned)((arow + mi*16)*ASTR + k8 + acol) << 2));
            }
            // B: two x4 -> {b[ni][0], b[ni][1], b[ni+1][0], b[ni+1][1]}
            #pragma unroll
            for (int np = 0; np < 2; np++)
                ldmx4(b[np], boff + ((unsigned)((brow + np*16)*BSTR + k8 + bcol) << 2));
            #pragma unroll
            for (int mi = 0; mi < 2; mi++) {
                mma1688(c_[mi][0], a[mi], &b[0][0]);
                mma1688(c_[mi][1], a[mi], &b[0][2]);
                mma1688(c_[mi][2], a[mi], &b[1][0]);
                mma1688(c_[mi][3], a[mi], &b[1][2]);
            }
        }
        if (cch < 15) STORE_CHUNK(buf ^ 1);
        __syncthreads();
    }

    // ---- epilogue ----
    #pragma unroll
    for (int mi = 0; mi < 2; mi++) {
        #pragma unroll
        for (int ni = 0; ni < 4; ni++) {
            const int jc = j0 + nw + ni*8 + 2*t;
            const int r0 = mw + mi*16 + g;
            const float* cr = c_[mi][ni];
            if (MODE == 1) {
                const int h = jc >> 5, hd = jc & 31;
                float b0 = d_bias2[camI*DIM + jc], b1 = d_bias2[camI*DIM + jc + 1];
                float* o0 = d_value + ((size_t)(camI*NH + h)*HWF + p0 + r0)*HD + hd;
                float* o1 = o0 + 8*HD;
                *(float2*)o0 = make_float2(cr[0] + b0, cr[1] + b1);
                *(float2*)o1 = make_float2(cr[2] + b0, cr[3] + b1);
            } else if (MODE == 2) {
                float b0, b1;
                if (jc < 128) { b0 = bias0[jc]; b1 = bias0[jc+1]; }
                else          { b0 = bias1[jc-128]; b1 = bias1[jc-127]; }
                int mr0 = m0 + r0, mr1 = mr0 + 8;
                if (mr0 < MROWS)
                    *(float2*)&d_offattn[(size_t)mr0*OAC + jc] = make_float2(cr[0]+b0, cr[1]+b1);
                if (mr1 < MROWS)
                    *(float2*)&d_offattn[(size_t)mr1*OAC + jc] = make_float2(cr[2]+b0, cr[3]+b1);
            } else {
                float b0 = bias0[jc] , b1 = bias0[jc+1];
                float e0 = d_bi2[jc], e1 = d_bi2[jc+1];
                int mr0 = m0 + r0, mr1 = mr0 + 8;
                if (mr0 < QN) {
                    float gf = d_gflag[mr0];
                    *(float2*)&C[(size_t)mr0*DIM + jc] =
                        make_float2(cr[0] + b0 + gf*e0, cr[1] + b1 + gf*e1);
                }
                if (mr1 < QN) {
                    float gf = d_gflag[mr1];
                    *(float2*)&C[(size_t)mr1*DIM + jc] =
                        make_float2(cr[2] + b0 + gf*e0, cr[3] + b1 + gf*e1);
                }
            }
        }
    }
    #undef LOAD_CHUNK
    #undef STORE_CHUNK
}

// ---------------- sampling + softmax + camera reduction ----------------
__global__ __launch_bounds__(256) void sample_kernel(const float* __restrict__ ref,
                                                     const void* __restrict__ mask) {
    const int q = blockIdx.x;
    const int tid = threadIdx.x;
    const int h = tid>>5, l = tid&31;
    const int corner = l>>3, c8 = l&7;
    const int ox = corner&1, oy = corner>>1;
    __shared__ float s_hit[NCAM];
    __shared__ float s_inv, s_g;
    if (tid < NCAM) {
        const int mode = d_mask_mode;
        size_t base = (size_t)(tid*QN + q)*8;
        int hit = mask_elem(mask, base+0, mode) | mask_elem(mask, base+2, mode) |
                  mask_elem(mask, base+4, mode) | mask_elem(mask, base+6, mode);
        s_hit[tid] = hit ? 1.f : 0.f;
    }
    __syncthreads();
    if (tid == 0) {
        float c = s_hit[0]+s_hit[1]+s_hit[2]+s_hit[3]+s_hit[4]+s_hit[5];
        s_g = (c > 0.f) ? 1.f : 0.f;
        s_inv = 1.f / fmaxf(c, 1.f);
    }
    __syncthreads();
    float ax=0.f, ay=0.f, az=0.f, aw=0.f;
    for (int camI = 0; camI < NCAM; camI++) {
        if (s_hit[camI] == 0.f) continue;
        const float* row = d_offattn + (size_t)(camI*QN + q)*OAC;
        float logit = row[128 + h*8 + c8];
        float ofx   = row[h*16 + c8*2];
        float ofy   = row[h*16 + c8*2 + 1];
        const float* rp = ref + ((size_t)(camI*QN + q)*4 + (c8&3))*2;
        float rx = rp[0], ry = rp[1];
        float mx = logit;
        mx = fmaxf(mx, __shfl_xor_sync(0xffffffffu, mx, 1, 8));
        mx = fmaxf(mx, __shfl_xor_sync(0xffffffffu, mx, 2, 8));
        mx = fmaxf(mx, __shfl_xor_sync(0xffffffffu, mx, 4, 8));
        float e = __expf(logit - mx);
        float sm = e;
        sm += __shfl_xor_sync(0xffffffffu, sm, 1, 8);
        sm += __shfl_xor_sync(0xffffffffu, sm, 2, 8);
        sm += __shfl_xor_sync(0xffffffffu, sm, 4, 8);
        float w = e / sm;
        const float* vb = d_value + (size_t)(camI*NH + h)*HWF*HD + c8*4;
        #pragma unroll
        for (int p = 0; p < 8; p++) {
            float wp  = __shfl_sync(0xffffffffu, w,   p, 8);
            float fx  = __shfl_sync(0xffffffffu, ofx, p, 8);
            float fy  = __shfl_sync(0xffffffffu, ofy, p, 8);
            float rxp = __shfl_sync(0xffffffffu, rx,  p, 8);
            float ryp = __shfl_sync(0xffffffffu, ry,  p, 8);
            float x = fmaf(rxp, (float)WFv, fx) - 0.5f;
            float y = fmaf(ryp, (float)HFv, fy) - 0.5f;
            float xf = floorf(x), yf = floorf(y);
            float dx = x - xf, dy = y - yf;
            int xi = (int)xf + ox;
            int yi = (int)yf + oy;
            float wx = ox ? dx : (1.f - dx);
            float wy = oy ? dy : (1.f - dy);
            bool valid = (xi >= 0) && (xi < WFv) && (yi >= 0) && (yi < HFv);
            float wc = valid ? (wp*wx*wy) : 0.f;
            int pix = min(max(yi,0),HFv-1)*WFv + min(max(xi,0),WFv-1);
            float4 v = *(const float4*)(vb + (size_t)pix*HD);
            ax = fmaf(wc, v.x, ax); ay = fmaf(wc, v.y, ay);
            az = fmaf(wc, v.z, az); aw = fmaf(wc, v.w, aw);
        }
    }
    ax += __shfl_xor_sync(0xffffffffu, ax, 8);  ax += __shfl_xor_sync(0xffffffffu, ax, 16);
    ay += __shfl_xor_sync(0xffffffffu, ay, 8);  ay += __shfl_xor_sync(0xffffffffu, ay, 16);
    az += __shfl_xor_sync(0xffffffffu, az, 8);  az += __shfl_xor_sync(0xffffffffu, az, 16);
    aw += __shfl_xor_sync(0xffffffffu, aw, 8);  aw += __shfl_xor_sync(0xffffffffu, aw, 16);
    if (l < 8) {
        float inv = s_inv;
        float4 o = make_float4(ax*inv, ay*inv, az*inv, aw*inv);
        *(float4*)&d_S[(size_t)q*DIM + h*HD + c8*4] = o;
    }
    if (tid == 0) d_gflag[q] = s_g;
}

// ---------------- launch ----------------
extern "C" void kernel_launch(void* const* d_in, const int* in_sizes, int n_in,
                              void* d_out, int out_size) {
    const float* queries = (const float*)d_in[0];
    const float* pos     = (const float*)d_in[1];
    const float* lvl     = (const float*)d_in[2];
    const float* camemb  = (const float*)d_in[3];
    const float* feat    = (const float*)d_in[4];
    const float* ref     = (const float*)d_in[5];
    const void*  mask    = (const void*)d_in[6];
    const float* W_value = (const float*)d_in[7];
    const float* b_value = (const float*)d_in[8];
    const float* W_off   = (const float*)d_in[9];
    const float* b_off   = (const float*)d_in[10];
    const float* W_attn  = (const float*)d_in[11];
    const float* b_attn  = (const float*)d_in[12];
    const float* W_inner = (const float*)d_in[13];
    const float* b_inner = (const float*)d_in[14];
    const float* W_out   = (const float*)d_in[15];
    const float* b_out   = (const float*)d_in[16];
    float* out = (float*)d_out;

    prep_a<<<NCAM + 1, DIM>>>(lvl, camemb, W_value, b_value, (const unsigned int*)mask);
    prep_b<<<DIM + 1, DIM>>>(W_out, W_inner, b_inner);
    gemm_tc<1><<<dim3(4, 132), 256>>>(feat, nullptr, W_value, nullptr,
                                      nullptr, nullptr, nullptr);
    gemm_tc<2><<<dim3(3, 469), 256>>>(queries, pos, W_off, W_attn,
                                      b_off, b_attn, nullptr);
    sample_kernel<<<QN, 256>>>(ref, mask);
    gemm_tc<3><<<dim3(4, 79), 256>>>(nullptr, nullptr, nullptr, nullptr,
                                     b_out, nullptr, out);
    (void)in_sizes; (void)n_in; (void)out_size;
}